// round 6
// baseline (speedup 1.0000x reference)
#include <cuda_runtime.h>

// Problem constants (fixed by setup_inputs: B=1, C=8, H=120, W=160, SKIP=8)
#define IMW 160
#define IMH 120
#define HW  19200
#define NC  8
#define NP  2400      // HW / SKIP_PIXELS
#define SKIPPIX 8
#define NCHUNK 12
#define CHUNK  200    // NP / NCHUNK
#define THR2 (0.9f * 0.9f)

// Scratch (device globals — no allocation allowed)
__device__ float4 g_pixA[NP];          // xs, ys, nx, ny
__device__ float  g_pixD[NP];          // depth = exp(vz)  (0 if invalid)
__device__ int    g_pixC[NP];          // class label (0 if invalid)
__device__ int    g_votes[NC * HW];    // [c][l]
__device__ float  g_dsum [NC * HW];    // [c][l]
__device__ int    g_nvalid[NC];

__global__ void init_kernel() {
    int i = blockIdx.x * blockDim.x + threadIdx.x;
    if (i < NC * HW) { g_votes[i] = 0; g_dsum[i] = 0.0f; }
    if (i < NC) g_nvalid[i] = 0;
}

__global__ void prep_kernel(const int* __restrict__ labels,
                            const int* __restrict__ masks,
                            const float* __restrict__ vp) {
    int p = blockIdx.x * blockDim.x + threadIdx.x;
    if (p >= NP) return;
    int idx = p * SKIPPIX;
    int lab = labels[idx];
    int m   = masks[idx];
    bool valid = (m > 0) && (lab > 0);
    float vx = vp[(lab * 3 + 0) * HW + idx];
    float vy = vp[(lab * 3 + 1) * HW + idx];
    float vz = vp[(lab * 3 + 2) * HW + idx];
    float nrm = sqrtf(vx * vx + vy * vy) + 1e-6f;
    float nx = vx / nrm;
    float ny = vy / nrm;
    float depth = expf(vz);
    if (!valid) { nx = 0.0f; ny = 0.0f; depth = 0.0f; lab = 0; }
    g_pixA[p] = make_float4((float)(idx % IMW), (float)(idx / IMW), nx, ny);
    g_pixD[p] = depth;
    g_pixC[p] = lab;
    if (valid) atomicAdd(&g_nvalid[lab], 1);
}

// Each thread owns 2 consecutive x-locations; each block.y owns a pixel chunk.
__global__ void __launch_bounds__(128) vote_kernel() {
    __shared__ float4 sA[CHUNK];
    __shared__ float  sD[CHUNK];
    __shared__ int    sC[CHUNK];
    int p0 = blockIdx.y * CHUNK;
    for (int i = threadIdx.x; i < CHUNK; i += blockDim.x) {
        sA[i] = g_pixA[p0 + i];
        sD[i] = g_pixD[p0 + i];
        sC[i] = g_pixC[p0 + i];
    }
    __syncthreads();

    int pair = blockIdx.x * blockDim.x + threadIdx.x;   // 0..9599 exactly
    int l0 = pair * 2;                                  // W=160 even -> same row
    float gx = (float)(l0 % IMW);
    float gy = (float)(l0 / IMW);

    int   v0[NC], v1[NC];
    float d0[NC], d1[NC];
#pragma unroll
    for (int c = 0; c < NC; c++) { v0[c] = 0; v1[c] = 0; d0[c] = 0.0f; d1[c] = 0.0f; }

#pragma unroll 4
    for (int i = 0; i < CHUNK; i++) {
        float4 a  = sA[i];
        float dx  = gx - a.x;
        float dy  = gy - a.y;
        float dxb = dx + 1.0f;
        float dot0 = dx  * a.z + dy * a.w;
        float dot1 = dxb * a.z + dy * a.w;
        float dy2 = dy * dy;
        float q0  = dx  * dx  + dy2;
        float q1  = dxb * dxb + dy2;
        // dot > 0.9*dist  <=>  dot>0 && dot^2 > 0.81*dist^2   (dist >= 0)
        bool h0 = (dot0 > 0.0f) && (dot0 * dot0 > THR2 * q0);
        bool h1 = (dot1 > 0.0f) && (dot1 * dot1 > THR2 * q1);
        if (h0 | h1) {
            int   c   = sC[i];
            float dep = sD[i];
            if (h0) { v0[c]++; d0[c] += dep; }
            if (h1) { v1[c]++; d1[c] += dep; }
        }
    }

#pragma unroll
    for (int c = 0; c < NC; c++) {
        if (v0[c]) {
            atomicAdd(&g_votes[c * HW + l0],     v0[c]);
            atomicAdd(&g_dsum [c * HW + l0],     d0[c]);
        }
        if (v1[c]) {
            atomicAdd(&g_votes[c * HW + l0 + 1], v1[c]);
            atomicAdd(&g_dsum [c * HW + l0 + 1], d1[c]);
        }
    }
}

// One block per class: argmax over HW locations (first-index tiebreak), then
// compute box5 + pose rows.
__global__ void reduce_kernel(const float* __restrict__ extents,
                              const float* __restrict__ poses,
                              const float* __restrict__ meta,
                              float* __restrict__ out) {
    int c = blockIdx.x;
    int t = threadIdx.x;
    unsigned long long best = 0ULL;
    for (int l = t; l < HW; l += blockDim.x) {
        unsigned v = (unsigned)g_votes[c * HW + l];
        unsigned long long key = ((unsigned long long)v << 32) | (unsigned)(0xFFFFFFFFu - l);
        if (key > best) best = key;
    }
    __shared__ unsigned long long sk[256];
    sk[t] = best;
    __syncthreads();
    for (int s = 128; s > 0; s >>= 1) {
        if (t < s) {
            unsigned long long o = sk[t + s];
            if (o > sk[t]) sk[t] = o;
        }
        __syncthreads();
    }
    if (t == 0) {
        unsigned long long k = sk[0];
        int   bl   = (int)(0xFFFFFFFFu - (unsigned)(k & 0xFFFFFFFFull));
        float vmax = (float)(unsigned)(k >> 32);
        float dsumv = g_dsum[c * HW + bl];
        float dbar = dsumv / fmaxf(vmax, 1.0f);
        float cx = (float)(bl % IMW);
        float cy = (float)(bl / IMW);
        float fx = meta[0], px = meta[2], fy = meta[4], py = meta[5];
        float e0 = extents[c * 3 + 0];
        float e1 = extents[c * 3 + 1];
        float e2 = extents[c * 3 + 2];
        float diag = sqrtf(e0 * e0 + e1 * e1 + e2 * e2);
        float safe_d = fmaxf(dbar, 1e-6f);
        float bw = diag * fx / safe_d;
        float bh = diag * fy / safe_d;
        float score = vmax / fmaxf((float)g_nvalid[c], 1.0f);

        float* box = out + c * 7;          // top_box row c (batch 0)
        box[0] = 0.0f;                     // batch index
        box[1] = (float)c;                 // class index
        box[2] = cx - bw * 0.5f;
        box[3] = cy - bh * 0.5f;
        box[4] = cx + bw * 0.5f;
        box[5] = cy + bh * 0.5f;
        box[6] = score;

        float* pp = out + NC * 7 + c * 7;  // top_pose row c
        pp[0] = poses[c * 7 + 0];
        pp[1] = poses[c * 7 + 1];
        pp[2] = poses[c * 7 + 2];
        pp[3] = poses[c * 7 + 3];
        pp[4] = (cx - px) * dbar / fmaxf(fx, 1e-6f);
        pp[5] = (cy - py) * dbar / fmaxf(fy, 1e-6f);
        pp[6] = dbar;
    }
}

extern "C" void kernel_launch(void* const* d_in, const int* in_sizes, int n_in,
                              void* d_out, int out_size) {
    const int*   labels  = (const int*)  d_in[0];
    const int*   masks   = (const int*)  d_in[1];
    const float* vp      = (const float*)d_in[2];
    const float* extents = (const float*)d_in[3];
    const float* poses   = (const float*)d_in[4];
    const float* meta    = (const float*)d_in[5];
    float* out = (float*)d_out;

    init_kernel<<<(NC * HW + 255) / 256, 256>>>();
    prep_kernel<<<(NP + 255) / 256, 256>>>(labels, masks, vp);
    vote_kernel<<<dim3(HW / 2 / 128, NCHUNK), 128>>>();
    reduce_kernel<<<NC, 256>>>(extents, poses, meta, out);
}